// round 12
// baseline (speedup 1.0000x reference)
#include <cuda_runtime.h>
#include <math.h>
#include <stdint.h>

#define S3 0.5773502691896258f
#define S2 0.7071067811865476f
#define EPS 1e-5f

// pre-rounded (tf32 rna) weights: W1[4096] | W2[57344] | Ws[98304] | Wv[65536]
__device__ float g_wr[225280];
#define W1R_OFF 0
#define W2R_OFF 4096
#define WSR_OFF 61440
#define WVR_OFF 159744

__device__ __forceinline__ float tf32r(float x) {
    uint32_t u;
    asm("cvt.rna.tf32.f32 %0, %1;" : "=r"(u) : "f"(x));
    return __uint_as_float(u);
}
// mma.sync m16n8k8 tf32: D += A(16x8) * B(8x8)^T, fp32 accum (baseline PTX, sm_80+)
__device__ __forceinline__ void mma8(float d[4], const uint32_t a[4], const uint32_t b[2]) {
    asm volatile(
        "mma.sync.aligned.m16n8k8.row.col.f32.tf32.tf32.f32 "
        "{%0,%1,%2,%3}, {%4,%5,%6,%7}, {%8,%9}, {%0,%1,%2,%3};"
        : "+f"(d[0]), "+f"(d[1]), "+f"(d[2]), "+f"(d[3])
        : "r"(a[0]), "r"(a[1]), "r"(a[2]), "r"(a[3]), "r"(b[0]), "r"(b[1]));
}
// Packed A tile: quad (mt,ks,lane) = [(r,k),(r,k+4),(r+8,k),(r+8,k+4)]
__device__ __forceinline__ void ldApk(uint32_t a[4], const float4* Ap, int mt, int ks, int lane) {
    float4 v = Ap[(mt * 8 + ks) * 32 + lane];
    a[0] = __float_as_uint(v.x);
    a[1] = __float_as_uint(v.z);
    a[2] = __float_as_uint(v.y);
    a[3] = __float_as_uint(v.w);
}
// B fragment from row-major [k][n] tile, stride SB (SB % 32 == 8) -> conflict-free
__device__ __forceinline__ void ldBk(uint32_t b[2], const float* Bs, int SB,
                                     int n0, int k0, int qr, int qc) {
    b[0] = __float_as_uint(Bs[(k0 + qc) * SB + n0 + qr]);
    b[1] = __float_as_uint(Bs[(k0 + qc + 4) * SB + n0 + qr]);
}
__device__ __forceinline__ float quad_sum(float v) {
    v += __shfl_xor_sync(0xffffffffu, v, 1);
    v += __shfl_xor_sync(0xffffffffu, v, 2);
    return v;
}
__device__ __forceinline__ void cpa16(uint32_t saddr, const float* g) {
    asm volatile("cp.async.ca.shared.global [%0], [%1], 16;" :: "r"(saddr), "l"(g));
}
#define CPA_COMMIT() asm volatile("cp.async.commit_group;" ::: "memory")
#define CPA_WAIT0()  asm volatile("cp.async.wait_group 0;" ::: "memory")
__device__ __forceinline__ uint32_t smem_u32(const void* p) {
    return (uint32_t)__cvta_generic_to_shared(p);
}

// ---------------------------------------------------------------------------
// K0: pre-round weights to tf32 (rna) into g_wr.
// ---------------------------------------------------------------------------
__global__ __launch_bounds__(256) void k0_round(
    const float* __restrict__ W1, const float* __restrict__ W2,
    const float* __restrict__ Ws, const float* __restrict__ Wv)
{
    int i = blockIdx.x * 256 + threadIdx.x;
    float v;
    if (i < 4096)        v = W1[i];
    else if (i < 61440)  v = W2[i - 4096];
    else if (i < 159744) v = Ws[i - 61440];
    else                 v = Wv[i - 159744];
    g_wr[i] = tf32r(v);
}

// ===========================================================================
// H stage: Ah (packed es) -> h = silu(LN(es@W1 + b1)), W1 in W1buf (SB=72).
// 512 thr: wm = wid&1, wn = wid>>1 (8 N-cols each).  HOOK fires after the
// h-MMA read barrier (safe to overwrite W1buf's twin etc).
// ===========================================================================
#define H_STAGE2(sm, Ah4, W1buf, redS, redQ, HOOK)                                \
{                                                                                 \
    float hacc[2][4];                                                             \
    _Pragma("unroll") for (int mt = 0; mt < 2; mt++)                              \
        _Pragma("unroll") for (int f = 0; f < 4; f++) hacc[mt][f] = 0.f;          \
    _Pragma("unroll") for (int ks = 0; ks < 8; ks++) {                            \
        uint32_t a0[4], a1[4], b[2];                                              \
        ldApk(a0, Ah4, wm * 2, ks, lane);                                         \
        ldApk(a1, Ah4, wm * 2 + 1, ks, lane);                                     \
        ldBk(b, W1buf, 72, wn * 8, ks * 8, qr, qc);                               \
        mma8(hacc[0], a0, b);                                                     \
        mma8(hacc[1], a1, b);                                                     \
    }                                                                             \
    __syncthreads();                                                              \
    HOOK;                                                                         \
    float cb[2], cgl[2], cBl[2];                                                  \
    _Pragma("unroll") for (int c = 0; c < 2; c++) {                               \
        int col = wn * 8 + qc * 2 + c;                                            \
        cb[c] = b1[col]; cgl[c] = lg[col]; cBl[c] = lb[col];                      \
    }                                                                             \
    _Pragma("unroll") for (int mt = 0; mt < 2; mt++)                              \
        _Pragma("unroll") for (int h = 0; h < 2; h++) {                           \
            float s = 0.f, q2 = 0.f;                                              \
            _Pragma("unroll") for (int c = 0; c < 2; c++) {                       \
                float v = hacc[mt][h * 2 + c] + cb[c];                            \
                hacc[mt][h * 2 + c] = v;                                          \
                s += v; q2 += v * v;                                              \
            }                                                                     \
            s = quad_sum(s); q2 = quad_sum(q2);                                   \
            if (qc == 0) {                                                        \
                int r = wm * 32 + mt * 16 + qr + h * 8;                           \
                redS[r * 8 + wn] = s; redQ[r * 8 + wn] = q2;                      \
            }                                                                     \
        }                                                                         \
    __syncthreads();                                                              \
    _Pragma("unroll") for (int mt = 0; mt < 2; mt++)                              \
        _Pragma("unroll") for (int h = 0; h < 2; h++) {                           \
            int r = wm * 32 + mt * 16 + qr + h * 8;                               \
            float s = 0.f, q2 = 0.f;                                              \
            _Pragma("unroll") for (int w8 = 0; w8 < 8; w8++) {                    \
                s += redS[r * 8 + w8]; q2 += redQ[r * 8 + w8];                    \
            }                                                                     \
            float mu = s * (1.f / 64.f);                                          \
            float rstd = rsqrtf(fmaxf(q2 * (1.f / 64.f) - mu * mu, 0.f) + EPS);   \
            int mtp = wm * 2 + mt;                                                \
            _Pragma("unroll") for (int c = 0; c < 2; c++) {                       \
                float v = (hacc[mt][h * 2 + c] - mu) * rstd * cgl[c] + cBl[c];    \
                v = v / (1.f + expf(-v));                                         \
                int col = wn * 8 + qc * 2 + c;                                    \
                int word = ((mtp * 8 + (col >> 3)) * 32 + qr * 4 + (col & 3)) * 4 \
                           + h * 2 + ((col >> 2) & 1);                            \
                sm[word] = tf32r(v);                                              \
            }                                                                     \
        }                                                                         \
    __syncthreads();                                                              \
}

// ---------------------------------------------------------------------------
// F2: scalar path.  smem(floats): Ah 0 | As 4096 | Bm 8192 (64x264)
//  | W2a 25088 | W2b 29696 (64x72) | wsa 34304 | wsb 38656 (64x68)
//  | ysm 43008 | redS 43264 | redQ 43776 | total 44288
// ---------------------------------------------------------------------------
#define F2_SMEM (44288 * 4)
__global__ __launch_bounds__(512, 1) void f2_s(
    const float* __restrict__ node, const float* __restrict__ eattr,
    const float* __restrict__ es,
    const float* __restrict__ b1, const float* __restrict__ lg,
    const float* __restrict__ lb, const float* __restrict__ roff,
    const float* __restrict__ bs, const float* __restrict__ gs,
    const float* __restrict__ gb, float* __restrict__ out, int E)
{
    extern __shared__ float sm[];
    float4* Ah4 = (float4*)sm;
    float4* As4 = (float4*)(sm + 4096);
    float*  Bm  = sm + 8192;
    float*  W2t[2] = { sm + 25088, sm + 29696 };
    float*  wsmb[2] = { sm + 34304, sm + 38656 };
    float*  ysm = sm + 43008;
    float* redS = sm + 43264;
    float* redQ = sm + 43776;
    const uint32_t BmU = smem_u32(Bm);
    const uint32_t W2U[2] = { smem_u32(W2t[0]), smem_u32(W2t[1]) };
    const int tid = threadIdx.x, wid = tid >> 5, lane = tid & 31;
    const int qr = lane >> 2, qc = lane & 3;
    const int e0 = blockIdx.x * 64;
    const int wm = wid & 1, wn = wid >> 1;
    const int Q = 6;

    auto colbase = [](int qq) { return (qq < 4) ? qq * 64 : 640 + (qq - 4) * 64; };
    auto commit_bm = [&](int qq) {
        for (int s = tid; s < 4096; s += 512) {
            int k = s >> 6, n4 = s & 63;
            cpa16(BmU + (uint32_t)(k * 264 + n4 * 4) * 4,
                  g_wr + WSR_OFF + (qq * 64 + k) * 256 + n4 * 4);
        }
        CPA_COMMIT();
    };
    auto commit_w2 = [&](int qq, int buf) {
        int nb = colbase(qq);
        for (int s = tid; s < 1024; s += 512) {
            int k = s >> 4, n4 = s & 15;
            cpa16(W2U[buf] + (uint32_t)(k * 72 + n4 * 4) * 4,
                  g_wr + W2R_OFF + k * 896 + nb + n4 * 4);
        }
        CPA_COMMIT();
    };
    // w-slice MMA: wsp[e][u] = h @ W2cols(qq) + roff   (issued alongside main MMA)
    auto wmma = [&](int qq, const float* W2p, float* wsp) {
        float wacc[2][4];
#pragma unroll
        for (int mt = 0; mt < 2; mt++)
#pragma unroll
            for (int f = 0; f < 4; f++) wacc[mt][f] = 0.f;
#pragma unroll
        for (int ks = 0; ks < 8; ks++) {
            uint32_t a0[4], a1[4], b[2];
            ldApk(a0, Ah4, wm * 2, ks, lane);
            ldApk(a1, Ah4, wm * 2 + 1, ks, lane);
            ldBk(b, W2p, 72, wn * 8, ks * 8, qr, qc);
            mma8(wacc[0], a0, b);
            mma8(wacc[1], a1, b);
        }
        int base = colbase(qq);
#pragma unroll
        for (int mt = 0; mt < 2; mt++)
#pragma unroll
            for (int h = 0; h < 2; h++) {
                int r = wm * 32 + mt * 16 + qr + h * 8;
#pragma unroll
                for (int c = 0; c < 2; c++) {
                    int u = wn * 8 + qc * 2 + c;
                    wsp[r * 68 + u] = wacc[mt][h * 2 + c] + roff[base + u];
                }
            }
    };
    auto buildAs = [&](int qq, const float* wsp) {
        for (int qd = tid; qd < 1024; qd += 512) {
            int mt = qd >> 8, kg = (qd >> 5) & 7, ln = qd & 31;
            int ea = mt * 16 + (ln >> 2), ka = kg * 8 + (ln & 3);
            float v[4];
#pragma unroll
            for (int t = 0; t < 4; t++) {
                int e = ea + (t >> 1) * 8, kk = ka + (t & 1) * 4;
                int ge = e0 + e;
                v[t] = 0.f;
                if (ge < E) {
                    if (qq < 4) {
                        v[t] = node[(size_t)ge * 640 + qq * 64 + kk] * ysm[e * 4]
                             * wsp[e * 68 + kk];
                    } else {
                        int j = (qq - 4) * 64 + kk;
                        const float* xp = node + (size_t)ge * 640 + 256 + 3 * j;
                        float d = xp[0] * ysm[e * 4 + 1] + xp[1] * ysm[e * 4 + 2]
                                + xp[2] * ysm[e * 4 + 3];
                        v[t] = S3 * d * wsp[e * 68 + kk];
                    }
                }
            }
            As4[qd] = make_float4(tf32r(v[0]), tf32r(v[1]), tf32r(v[2]), tf32r(v[3]));
        }
    };

    // group0: W1 -> W2t[0], W2c(0) -> W2t[1], Bm(0)
    for (int s = tid; s < 1024; s += 512) {
        int k = s >> 4, n4 = s & 15;
        cpa16(W2U[0] + (uint32_t)(k * 72 + n4 * 4) * 4, g_wr + W1R_OFF + k * 64 + n4 * 4);
        cpa16(W2U[1] + (uint32_t)(k * 72 + n4 * 4) * 4, g_wr + W2R_OFF + k * 896 + n4 * 4);
    }
    for (int s = tid; s < 4096; s += 512) {
        int k = s >> 6, n4 = s & 63;
        cpa16(BmU + (uint32_t)(k * 264 + n4 * 4) * 4, g_wr + WSR_OFF + k * 256 + n4 * 4);
    }
    CPA_COMMIT();
    if (tid < 256) {
        int ge = e0 + (tid >> 2);
        ysm[tid] = (ge < E) ? eattr[(size_t)ge * 4 + (tid & 3)] : 0.f;
    }
    for (int qd = tid; qd < 1024; qd += 512) {
        int mt = qd >> 8, kg = (qd >> 5) & 7, ln = qd & 31;
        int ea = e0 + mt * 16 + (ln >> 2), ka = kg * 8 + (ln & 3);
        int eb = ea + 8;
        float v00 = (ea < E) ? es[(size_t)ea * 64 + ka] : 0.f;
        float v01 = (ea < E) ? es[(size_t)ea * 64 + ka + 4] : 0.f;
        float v10 = (eb < E) ? es[(size_t)eb * 64 + ka] : 0.f;
        float v11 = (eb < E) ? es[(size_t)eb * 64 + ka + 4] : 0.f;
        Ah4[qd] = make_float4(tf32r(v00), tf32r(v01), tf32r(v10), tf32r(v11));
    }
    CPA_WAIT0();
    __syncthreads();

    H_STAGE2(sm, Ah4, W2t[0], redS, redQ, commit_w2(1, 0))

    wmma(0, W2t[1], wsmb[0]);
    __syncthreads();
    buildAs(0, wsmb[0]);

    float acc[2][4][4];
#pragma unroll
    for (int mt = 0; mt < 2; mt++)
#pragma unroll
        for (int nt = 0; nt < 4; nt++)
#pragma unroll
            for (int f = 0; f < 4; f++) acc[mt][nt][f] = 0.f;

    for (int q = 0; q < Q; q++) {
        CPA_WAIT0();
        __syncthreads();
        if (q + 2 < Q) commit_w2(q + 2, (q + 1) & 1);
        if (q + 1 < Q) wmma(q + 1, W2t[q & 1], wsmb[(q + 1) & 1]);
#pragma unroll
        for (int ks = 0; ks < 8; ks++) {
            uint32_t a0[4], a1[4];
            ldApk(a0, As4, wm * 2, ks, lane);
            ldApk(a1, As4, wm * 2 + 1, ks, lane);
#pragma unroll
            for (int nt = 0; nt < 4; nt++) {
                uint32_t b[2];
                ldBk(b, Bm, 264, wn * 32 + nt * 8, ks * 8, qr, qc);
                mma8(acc[0][nt], a0, b);
                mma8(acc[1][nt], a1, b);
            }
        }
        __syncthreads();
        if (q + 1 < Q) {
            commit_bm(q + 1);
            buildAs(q + 1, wsmb[(q + 1) & 1]);
        }
    }

    // epilogue: +bias, LN over 256 cols (cross 8 wn warps), write
    float cbv[8], cgv[8], cBv[8];
#pragma unroll
    for (int nt = 0; nt < 4; nt++)
#pragma unroll
        for (int c = 0; c < 2; c++) {
            int col = wn * 32 + nt * 8 + qc * 2 + c;
            cbv[nt * 2 + c] = bs[col]; cgv[nt * 2 + c] = gs[col]; cBv[nt * 2 + c] = gb[col];
        }
#pragma unroll
    for (int mt = 0; mt < 2; mt++)
#pragma unroll
        for (int h = 0; h < 2; h++) {
            float s = 0.f, q2 = 0.f;
#pragma unroll
            for (int nt = 0; nt < 4; nt++)
#pragma unroll
                for (int c = 0; c < 2; c++) {
                    float v = acc[mt][nt][h * 2 + c] + cbv[nt * 2 + c];
                    acc[mt][nt][h * 2 + c] = v;
                    s += v; q2 += v * v;
                }
            s = quad_sum(s); q2 = quad_sum(q2);
            if (qc == 0) {
                int r = wm * 32 + mt * 16 + qr + h * 8;
                redS[r * 8 + wn] = s; redQ[r * 8 + wn] = q2;
            }
        }
    __syncthreads();
#pragma unroll
    for (int mt = 0; mt < 2; mt++)
#pragma unroll
        for (int h = 0; h < 2; h++) {
            int r = wm * 32 + mt * 16 + qr + h * 8, ge = e0 + r;
            float s = 0.f, q2 = 0.f;
#pragma unroll
            for (int w8 = 0; w8 < 8; w8++) { s += redS[r * 8 + w8]; q2 += redQ[r * 8 + w8]; }
            float mu = s * (1.f / 256.f);
            float rstd = rsqrtf(fmaxf(q2 * (1.f / 256.f) - mu * mu, 0.f) + EPS);
            if (ge < E) {
#pragma unroll
                for (int nt = 0; nt < 4; nt++) {
                    int col = wn * 32 + nt * 8 + qc * 2;
                    float2 v;
                    v.x = (acc[mt][nt][h * 2] - mu) * rstd * cgv[nt * 2] + cBv[nt * 2];
                    v.y = (acc[mt][nt][h * 2 + 1] - mu) * rstd * cgv[nt * 2 + 1] + cBv[nt * 2 + 1];
                    *(float2*)&out[(size_t)ge * 640 + col] = v;
                }
            }
        }
}

// ---------------------------------------------------------------------------
// F3: vector path, 4-plane.  smem(floats): Ah 0 | A0 4096 | A1 8192 | A2 12288
//  | Bm0 16384 | Bm1 25088 (64x136) | W2a 33792 | W2b 38400 (64x72)
//  | wsa 43008 | wsb 47360 (64x68) | ysm 51712 | redS 51968 | redQ 52480
//  | total 52992
// ---------------------------------------------------------------------------
#define F3_SMEM (52992 * 4)
__global__ __launch_bounds__(512, 1) void f3_v(
    const float* __restrict__ node, const float* __restrict__ eattr,
    const float* __restrict__ es,
    const float* __restrict__ b1, const float* __restrict__ lg,
    const float* __restrict__ lb, const float* __restrict__ roff,
    const float* __restrict__ gv, float* __restrict__ out, int E)
{
    extern __shared__ float sm[];
    float4* Ah4 = (float4*)sm;
    float4* A04 = (float4*)(sm + 4096);
    float4* A14 = (float4*)(sm + 8192);
    float4* A24 = (float4*)(sm + 12288);
    float*  Bmb[2] = { sm + 16384, sm + 25088 };
    float*  W2t[2] = { sm + 33792, sm + 38400 };
    float*  wsmb[2] = { sm + 43008, sm + 47360 };
    float*  ysm = sm + 51712;
    float* redS = sm + 51968;
    float* redQ = sm + 52480;
    const uint32_t BmU[2] = { smem_u32(Bmb[0]), smem_u32(Bmb[1]) };
    const uint32_t W2U[2] = { smem_u32(W2t[0]), smem_u32(W2t[1]) };
    const int tid = threadIdx.x, wid = tid >> 5, lane = tid & 31;
    const int qr = lane >> 2, qc = lane & 3;
    const int e0 = blockIdx.x * 64;
    const int wm = wid & 1, wn = wid >> 1;
    const int n0 = wn * 16;
    const int Q = 8;

    auto colbase = [](int qq) {
        return (qq < 4) ? 256 + qq * 64 : (qq < 6 ? 512 + (qq - 4) * 64
                                                  : 768 + (qq - 6) * 64);
    };
    // one group: Bm(qq)->Bmb[qq&1] and (if valid) W2c(qq+1)->W2t[qq&1]
    auto commit_next = [&](int qq) {
        for (int s = tid; s < 2048; s += 512) {
            int k = s >> 5, n4 = s & 31;
            cpa16(BmU[qq & 1] + (uint32_t)(k * 136 + n4 * 4) * 4,
                  g_wr + WVR_OFF + (qq * 64 + k) * 128 + n4 * 4);
        }
        if (qq + 1 < Q) {
            int nb = colbase(qq + 1);
            for (int s = tid; s < 1024; s += 512) {
                int k = s >> 4, n4 = s & 15;
                cpa16(W2U[qq & 1] + (uint32_t)(k * 72 + n4 * 4) * 4,
                      g_wr + W2R_OFF + k * 896 + nb + n4 * 4);
            }
        }
        CPA_COMMIT();
    };
    auto wmma = [&](int qq, const float* W2p, float* wsp) {
        float wacc[2][4];
#pragma unroll
        for (int mt = 0; mt < 2; mt++)
#pragma unroll
            for (int f = 0; f < 4; f++) wacc[mt][f] = 0.f;
#pragma unroll
        for (int ks = 0; ks < 8; ks++) {
            uint32_t a0[4], a1[4], b[2];
            ldApk(a0, Ah4, wm * 2, ks, lane);
            ldApk(a1, Ah4, wm * 2 + 1, ks, lane);
            ldBk(b, W2p, 72, wn * 8, ks * 8, qr, qc);
            mma8(wacc[0], a0, b);
            mma8(wacc[1], a1, b);
        }
        int base = colbase(qq);
#pragma unroll
        for (int mt = 0; mt < 2; mt++)
#pragma unroll
            for (int h = 0; h < 2; h++) {
                int r = wm * 32 + mt * 16 + qr + h * 8;
#pragma unroll
                for (int c = 0; c < 2; c++) {
                    int u = wn * 8 + qc * 2 + c;
                    wsp[r * 68 + u] = wacc[mt][h * 2 + c] + roff[base + u];
                }
            }
    };
    auto buildA = [&](int qq, const float* wsp) {
        if (qq < 4) {
            for (int qd = tid; qd < 1024; qd += 512) {
                int mt = qd >> 8, kg = (qd >> 5) & 7, ln = qd & 31;
                int ea = mt * 16 + (ln >> 2), ka = kg * 8 + (ln & 3);
                float v[4];
#pragma unroll
                for (int t = 0; t < 4; t++) {
                    int e = ea + (t >> 1) * 8, kk = ka + (t & 1) * 4;
                    int ge = e0 + e;
                    v[t] = (ge < E)
                         ? node[(size_t)ge * 640 + qq * 64 + kk] * wsp[e * 68 + kk]
                         : 0.f;
                }
                A04[qd] = make_float4(tf32r(v[0]), tf32r(v[1]), tf32r(v[2]), tf32r(v[3]));
            }
        } else {
            for (int qd = tid; qd < 1024; qd += 512) {
                int mt = qd >> 8, kg = (qd >> 5) & 7, ln = qd & 31;
                int ea = mt * 16 + (ln >> 2), ka = kg * 8 + (ln & 3);
                float a0[4], a1[4], a2[4];
#pragma unroll
                for (int t = 0; t < 4; t++) {
                    int e = ea + (t >> 1) * 8, kk = ka + (t & 1) * 4;
                    int ge = e0 + e;
                    a0[t] = a1[t] = a2[t] = 0.f;
                    if (ge < E) {
                        if (qq < 6) {
                            int j = (qq - 4) * 64 + kk;
                            const float* xp = node + (size_t)ge * 640 + 256 + 3 * j;
                            float f = ysm[e * 4] * wsp[e * 68 + kk];
                            a0[t] = xp[0] * f; a1[t] = xp[1] * f; a2[t] = xp[2] * f;
                        } else {
                            int j = (qq - 6) * 64 + kk;
                            const float* xp = node + (size_t)ge * 640 + 256 + 3 * j;
                            float x0v = xp[0], x1v = xp[1], x2v = xp[2];
                            float z0 = ysm[e * 4 + 1], z1 = ysm[e * 4 + 2], z2 = ysm[e * 4 + 3];
                            float f = S2 * wsp[e * 68 + kk];
                            a0[t] = (x1v * z2 - x2v * z1) * f;
                            a1[t] = (x2v * z0 - x0v * z2) * f;
                            a2[t] = (x0v * z1 - x1v * z0) * f;
                        }
                    }
                }
                A04[qd] = make_float4(tf32r(a0[0]), tf32r(a0[1]), tf32r(a0[2]), tf32r(a0[3]));
                A14[qd] = make_float4(tf32r(a1[0]), tf32r(a1[1]), tf32r(a1[2]), tf32r(a1[3]));
                A24[qd] = make_float4(tf32r(a2[0]), tf32r(a2[1]), tf32r(a2[2]), tf32r(a2[3]));
            }
        }
    };

    // group0: W1 -> W2t[0], W2c(0) -> W2t[1], Bm(0) -> Bmb[0]
    for (int s = tid; s < 1024; s += 512) {
        int k = s >> 4, n4 = s & 15;
        cpa16(W2U[0] + (uint32_t)(k * 72 + n4 * 4) * 4, g_wr + W1R_OFF + k * 64 + n4 * 4);
        cpa16(W2U[1] + (uint32_t)(k * 72 + n4 * 4) * 4,
              g_wr + W2R_OFF + k * 896 + 256 + n4 * 4);
    }
    for (int s = tid; s < 2048; s += 512) {
        int k = s >> 5, n4 = s & 31;
        cpa16(BmU[0] + (uint32_t)(k * 136 + n4 * 4) * 4,
              g_wr + WVR_OFF + k * 128 + n4 * 4);
    }
    CPA_COMMIT();
    if (tid < 256) {
        int ge = e0 + (tid >> 2);
        ysm[tid] = (ge < E) ? eattr[(size_t)ge * 4 + (tid & 3)] : 0.f;
    }
    for (int qd = tid; qd < 1024; qd += 512) {
        int mt = qd >> 8, kg = (qd >> 5) & 7, ln = qd & 31;
        int ea = e0 + mt * 16 + (ln >> 2), ka = kg * 8 + (ln & 3);
        int eb = ea + 8;
        float v00 = (ea < E) ? es[(size_t)ea * 64 + ka] : 0.f;
        float v01 = (ea < E) ? es[(size_t)ea * 64 + ka + 4] : 0.f;
        float v10 = (eb < E) ? es[(size_t)eb * 64 + ka] : 0.f;
        float v11 = (eb < E) ? es[(size_t)eb * 64 + ka + 4] : 0.f;
        Ah4[qd] = make_float4(tf32r(v00), tf32r(v01), tf32r(v10), tf32r(v11));
    }
    CPA_WAIT0();
    __syncthreads();

    // H stage; hook commits W2c(1) -> W2t[0] (W1 consumed)
    H_STAGE2(sm, Ah4, W2t[0], redS, redQ, ({
        int nb = colbase(1);
        for (int s = tid; s < 1024; s += 512) {
            int k = s >> 4, n4 = s & 15;
            cpa16(W2U[0] + (uint32_t)(k * 72 + n4 * 4) * 4,
                  g_wr + W2R_OFF + k * 896 + nb + n4 * 4);
        }
        CPA_COMMIT();
    }))

    wmma(0, W2t[1], wsmb[0]);
    __syncthreads();
    buildA(0, wsmb[0]);

    float accR[2][2][4];
    float accM[3][2][2][4];
#pragma unroll
    for (int mt = 0; mt < 2; mt++)
#pragma unroll
        for (int nt = 0; nt < 2; nt++)
#pragma unroll
            for (int f = 0; f < 4; f++) {
                accR[mt][nt][f] = 0.f;
#pragma unroll
                for (int m = 0; m < 3; m++) accM[m][mt][nt][f] = 0.f;
            }

    for (int q = 0; q < Q; q++) {
        CPA_WAIT0();
        __syncthreads();
        if (q + 1 < Q) {
            commit_next(q + 1);                      // Bm(q+1), W2c(q+2)
            wmma(q + 1, W2t[q & 1], wsmb[(q + 1) & 1]);
        }
        const float* Bq = Bmb[q & 1];
        if (q < 4) {
#pragma unroll
            for (int ks = 0; ks < 8; ks++) {
                uint32_t a0[4], a1[4];
                ldApk(a0, A04, wm * 2, ks, lane);
                ldApk(a1, A04, wm * 2 + 1, ks, lane);
#pragma unroll
                for (int nt = 0; nt < 2; nt++) {
                    uint32_t b[2];
                    ldBk(b, Bq, 136, n0 + nt * 8, ks * 8, qr, qc);
                    mma8(accR[0][nt], a0, b);
                    mma8(accR[1][nt], a1, b);
                }
            }
        } else {
#pragma unroll
            for (int ks = 0; ks < 8; ks++) {
                uint32_t b[2][2];
#pragma unroll
                for (int nt = 0; nt < 2; nt++) ldBk(b[nt], Bq, 136, n0 + nt * 8, ks * 8, qr, qc);
                const float4* Ap[3] = {A04, A14, A24};
#pragma unroll
                for (int m = 0; m < 3; m++) {
                    uint32_t a0[4], a1[4];
                    ldApk(a0, Ap[m], wm * 2, ks, lane);
                    ldApk(a1, Ap[m], wm * 2 + 1, ks, lane);
#pragma unroll
                    for (int nt = 0; nt < 2; nt++) {
                        mma8(accM[m][0][nt], a0, b[nt]);
                        mma8(accM[m][1][nt], a1, b[nt]);
                    }
                }
            }
        }
        __syncthreads();
        if (q + 1 < Q) buildA(q + 1, wsmb[(q + 1) & 1]);
    }

    // epilogue: fold R plane, sumsq, norm, write
#pragma unroll
    for (int mt = 0; mt < 2; mt++)
#pragma unroll
        for (int h = 0; h < 2; h++) {
            int e = wm * 32 + mt * 16 + qr + h * 8;
            float z0 = ysm[e * 4 + 1], z1 = ysm[e * 4 + 2], z2 = ysm[e * 4 + 3];
            float s = 0.f;
#pragma unroll
            for (int nt = 0; nt < 2; nt++)
#pragma unroll
                for (int c = 0; c < 2; c++) {
                    float R = accR[mt][nt][h * 2 + c];
                    float v0 = z0 * R + accM[0][mt][nt][h * 2 + c];
                    float v1 = z1 * R + accM[1][mt][nt][h * 2 + c];
                    float v2 = z2 * R + accM[2][mt][nt][h * 2 + c];
                    accM[0][mt][nt][h * 2 + c] = v0;
                    accM[1][mt][nt][h * 2 + c] = v1;
                    accM[2][mt][nt][h * 2 + c] = v2;
                    s += v0 * v0 + v1 * v1 + v2 * v2;
                }
            s = quad_sum(s);
            if (qc == 0) redQ[e * 8 + wn] = s;
        }
    __syncthreads();
    float cg[4];
#pragma unroll
    for (int nt = 0; nt < 2; nt++)
#pragma unroll
        for (int c = 0; c < 2; c++) cg[nt * 2 + c] = gv[n0 + nt * 8 + qc * 2 + c];
#pragma unroll
    for (int mt = 0; mt < 2; mt++)
#pragma unroll
        for (int h = 0; h < 2; h++) {
            int e = wm * 32 + mt * 16 + qr + h * 8, ge = e0 + e;
            float qt = 0.f;
#pragma unroll
            for (int w8 = 0; w8 < 8; w8++) qt += redQ[e * 8 + w8];
            float rstd = rsqrtf(qt * (1.f / 384.f) + EPS);
            if (ge < E) {
                float* ob = out + (size_t)ge * 640 + 256;
#pragma unroll
                for (int nt = 0; nt < 2; nt++)
#pragma unroll
                    for (int c = 0; c < 2; c++) {
                        int col = n0 + nt * 8 + qc * 2 + c;
                        float g = cg[nt * 2 + c] * rstd;
                        ob[3 * col + 0] = accM[0][mt][nt][h * 2 + c] * g;
                        ob[3 * col + 1] = accM[1][mt][nt][h * 2 + c] * g;
                        ob[3 * col + 2] = accM[2][mt][nt][h * 2 + c] * g;
                    }
            }
        }
}

// ---------------------------------------------------------------------------
extern "C" void kernel_launch(void* const* d_in, const int* in_sizes, int n_in,
                              void* d_out, int out_size)
{
    const float* node  = (const float*)d_in[0];   // (E, 640)
    const float* eattr = (const float*)d_in[1];   // (E, 4)
    const float* escal = (const float*)d_in[2];   // (E, 64)
    const float* rW1   = (const float*)d_in[3];   // (64, 64)
    const float* rb1   = (const float*)d_in[4];   // (64,)
    const float* rlg   = (const float*)d_in[5];   // (64,)
    const float* rlb   = (const float*)d_in[6];   // (64,)
    const float* rW2   = (const float*)d_in[7];   // (64, 896)
    const float* roff  = (const float*)d_in[8];   // (896,)
    const float* Ws    = (const float*)d_in[9];   // (384, 256)
    const float* bs    = (const float*)d_in[10];  // (256,)
    const float* Wv    = (const float*)d_in[11];  // (512, 128)
    const float* gs    = (const float*)d_in[12];  // (256,)
    const float* gb    = (const float*)d_in[13];  // (256,)
    const float* gv    = (const float*)d_in[14];  // (128,)
    float* out = (float*)d_out;

    const int E = in_sizes[1] / 4;
    const int nb64 = (E + 63) / 64;

    cudaFuncSetAttribute(f2_s, cudaFuncAttributeMaxDynamicSharedMemorySize, F2_SMEM);
    cudaFuncSetAttribute(f3_v, cudaFuncAttributeMaxDynamicSharedMemorySize, F3_SMEM);

    k0_round<<<880, 256>>>(rW1, rW2, Ws, Wv);
    f2_s<<<nb64, 512, F2_SMEM>>>(node, eattr, escal, rb1, rlg, rlb, roff,
                                 bs, gs, gb, out, E);
    f3_v<<<nb64, 512, F3_SMEM>>>(node, eattr, escal, rb1, rlg, rlb, roff,
                                 gv, out, E);
}